// round 13
// baseline (speedup 1.0000x reference)
#include <cuda_runtime.h>
#include <cuda_fp16.h>
#include <cstdint>

#define TOKENS 8192
#define IN_F   4096
#define OUT_F  4096
#define BM 128
#define BN 256
#define BK 128
#define NK_ITERS (IN_F / BK)    // 32
#define LDSR (BK + 8)           // 136 halves = 272B pitch (272 % 128 = 16 -> conflict-free ldmatrix)
#define STAGES 2
#define A_STAGE_ELEMS (BM * LDSR)   // 17408
#define B_STAGE_ELEMS (BN * LDSR)   // 34816
#define SMEM_BYTES (STAGES * (A_STAGE_ELEMS + B_STAGE_ELEMS) * 2)   // 208896 (204 KB)
#define N_TILES ((TOKENS / BM) * (OUT_F / BN))   // 1024
#define TILES_X (OUT_F / BN)                     // 16

// ---------------- scratch (device globals: allowed; no allocs) -------------
__device__ __align__(16) __half g_Xh[(size_t)TOKENS * IN_F];   // 64 MB fp16 activations
__device__ __align__(16) __half g_Wh[(size_t)OUT_F * IN_F];    // 32 MB fp16 dequant weights

__device__ __forceinline__ uint32_t smem_u32(const void* p) {
    return (uint32_t)__cvta_generic_to_shared(p);
}

__device__ __forceinline__ void ldm_x4(uint32_t& r0, uint32_t& r1,
                                       uint32_t& r2, uint32_t& r3, uint32_t addr) {
    asm volatile("ldmatrix.sync.aligned.m8n8.x4.shared.b16 {%0,%1,%2,%3}, [%4];"
                 : "=r"(r0), "=r"(r1), "=r"(r2), "=r"(r3) : "r"(addr));
}

__device__ __forceinline__ void mma16816(float* c, const uint32_t* a,
                                         uint32_t b0, uint32_t b1) {
    asm volatile(
        "mma.sync.aligned.m16n8k16.row.col.f32.f16.f16.f32 "
        "{%0,%1,%2,%3}, {%4,%5,%6,%7}, {%8,%9}, {%0,%1,%2,%3};"
        : "+f"(c[0]), "+f"(c[1]), "+f"(c[2]), "+f"(c[3])
        : "r"(a[0]), "r"(a[1]), "r"(a[2]), "r"(a[3]), "r"(b0), "r"(b1));
}

// ---------------- fused prep kernel -----------------------------------------
// Same element count for both jobs: TOKENS*IN_F/4 = OUT_F*IN_F/2 = 8.39M.
__global__ void prep_kernel(const float* __restrict__ x,
                            const int* __restrict__ wp,
                            const float* __restrict__ ws) {
    size_t i = (size_t)blockIdx.x * blockDim.x + threadIdx.x;
    if (i >= (size_t)TOKENS * IN_F / 4) return;
    // X: one float4 -> 2x half2
    {
        float4 v = reinterpret_cast<const float4*>(x)[i];
        __half2* out = reinterpret_cast<__half2*>(g_Xh);
        out[2 * i]     = __floats2half2_rn(v.x, v.y);
        out[2 * i + 1] = __floats2half2_rn(v.z, v.w);
    }
    // W: one packed byte-pair (int32 holding uint8) -> half2
    {
        int n = (int)(i >> 11);          // / 2048
        int j = (int)(i & 2047);
        int p = wp[i];
        float s = ws[n * (IN_F / 128) + (j >> 6)];   // group = (2j)/128 = j/64
        float lo = (float)((p & 15) - 8) * s;
        float hi = (float)(((p >> 4) & 15) - 8) * s;
        reinterpret_cast<__half2*>(g_Wh)[i] = __floats2half2_rn(lo, hi);
    }
}

// ---------------- persistent HMMA GEMM ---------------------------------------
// C[M,N] = Xh[M,K] @ Wh[N,K]^T. CTA tile 128x256, 8 warps (2x4), warp tile
// 64x64, BK=128, 2-stage double-buffer. Persistent: each CTA loops over
// tiles (t += gridDim.x). At the last K-iter of a tile, the refill slots
// prefetch the NEXT tile's stage 0 (stage parity: 32 iters -> next_st = 0),
// so the cp.async pipeline never drains across tiles; the epilogue runs
// between commit and the next tile's wait, providing slack.
__global__ void __launch_bounds__(256, 1)
gemm_hmma_kernel(float* __restrict__ C) {
    extern __shared__ __align__(16) __half smem[];
    __half* sA = smem;                                 // STAGES x BM x LDSR
    __half* sB = smem + STAGES * A_STAGE_ELEMS;        // STAGES x BN x LDSR

    const int tid = threadIdx.x;
    const int wid = tid >> 5;
    const int lid = tid & 31;
    const int quad = lid >> 3;
    const int l8 = lid & 7;
    const int m_off = (wid & 1) * 64;      // 2 warp rows
    const int n_off = (wid >> 1) * 64;     // 4 warp cols

    // Stage loader eighth e (0..7) for a given tile's base pointers.
    auto load_eighth = [&](const __half* baseA, const __half* baseB,
                           int st, int kc, int e) {
        const __half* pa = baseA + kc * BK;
        const __half* pb = baseB + kc * BK;
        __half* da = sA + st * A_STAGE_ELEMS;
        __half* db = sB + st * B_STAGE_ELEMS;
        {
            int chunk = tid + 256 * e;
            int row = chunk >> 4, ch = chunk & 15;
            uint32_t dst = smem_u32(da + row * LDSR + ch * 8);
            asm volatile("cp.async.cg.shared.global [%0], [%1], 16;"
                         :: "r"(dst), "l"((const void*)(pa + (size_t)row * IN_F + ch * 8)));
        }
#pragma unroll
        for (int i = 0; i < 2; i++) {
            int chunk = tid + 256 * (2 * e + i);
            int row = chunk >> 4, ch = chunk & 15;
            uint32_t dst = smem_u32(db + row * LDSR + ch * 8);
            asm volatile("cp.async.cg.shared.global [%0], [%1], 16;"
                         :: "r"(dst), "l"((const void*)(pb + (size_t)row * IN_F + ch * 8)));
        }
    };

    const int first_t = blockIdx.x;
    const int stride = gridDim.x;

    // Prologue: load stage 0 of the first tile.
    {
        const __half* baseA = g_Xh + (size_t)((first_t >> 4) * BM) * IN_F;
        const __half* baseB = g_Wh + (size_t)((first_t & 15) * BN) * IN_F;
#pragma unroll
        for (int e = 0; e < 8; e++) load_eighth(baseA, baseB, 0, 0, e);
        asm volatile("cp.async.commit_group;");
    }

    for (int t = first_t; t < N_TILES; t += stride) {
        const int m0 = (t >> 4) * BM;      // TILES_X = 16
        const int n0 = (t & 15) * BN;
        const __half* baseA = g_Xh + (size_t)m0 * IN_F;
        const __half* baseB = g_Wh + (size_t)n0 * IN_F;

        const int tn = t + stride;
        const bool has_next = tn < N_TILES;
        const __half* nbaseA = has_next ? g_Xh + (size_t)(tn >> 4) * BM * IN_F : baseA;
        const __half* nbaseB = has_next ? g_Wh + (size_t)(tn & 15) * BN * IN_F : baseB;

        float acc[4][8][4];
#pragma unroll
        for (int mi = 0; mi < 4; mi++)
#pragma unroll
            for (int nf = 0; nf < 8; nf++)
#pragma unroll
                for (int r = 0; r < 4; r++) acc[mi][nf][r] = 0.0f;

        for (int kc = 0; kc < NK_ITERS; kc++) {
            asm volatile("cp.async.wait_group 0;");   // stage cur complete
            __syncthreads();                          // all warps done with other stage

            const int cur = kc & 1;
            const __half* cA = sA + cur * A_STAGE_ELEMS;
            const __half* cB = sB + cur * B_STAGE_ELEMS;
            const int next_st = cur ^ 1;
            const bool intra = (kc + 1 < NK_ITERS);
            const bool pre = (!intra) && has_next;    // last iter: prefetch next tile st 0

#pragma unroll
            for (int kk = 0; kk < 8; kk++) {
                const int k0 = kk * 16;
                uint32_t a[4][4];
#pragma unroll
                for (int mi = 0; mi < 4; mi++) {
                    uint32_t addr = smem_u32(
                        cA + (m_off + mi * 16 + (quad & 1) * 8 + l8) * LDSR
                           + k0 + (quad >> 1) * 8);
                    ldm_x4(a[mi][0], a[mi][1], a[mi][2], a[mi][3], addr);
                }
                uint32_t b[4][4];
#pragma unroll
                for (int nb = 0; nb < 4; nb++) {
                    uint32_t addr = smem_u32(
                        cB + (n_off + nb * 16 + (quad >> 1) * 8 + l8) * LDSR
                           + k0 + (quad & 1) * 8);
                    ldm_x4(b[nb][0], b[nb][1], b[nb][2], b[nb][3], addr);
                }
#pragma unroll
                for (int mi = 0; mi < 4; mi++)
#pragma unroll
                    for (int nf = 0; nf < 8; nf++) {
                        const uint32_t* bf = &b[nf >> 1][(nf & 1) * 2];
                        mma16816(acc[mi][nf], a[mi], bf[0], bf[1]);
                    }

                // Front-loaded refill (round-12 proven): 2 eighths per kk for
                // kk=0..3, commit at kk=3. On the last K-iter, the same slots
                // prefetch the next tile's stage 0 (next_st == 0 there).
                if (kk < 4) {
                    if (intra) {
                        load_eighth(baseA, baseB, next_st, kc + 1, 2 * kk);
                        load_eighth(baseA, baseB, next_st, kc + 1, 2 * kk + 1);
                    } else if (pre) {
                        load_eighth(nbaseA, nbaseB, next_st, 0, 2 * kk);
                        load_eighth(nbaseA, nbaseB, next_st, 0, 2 * kk + 1);
                    }
                }
                if (kk == 3) asm volatile("cp.async.commit_group;");
            }
        }

        // Epilogue (registers only — no SMEM reads, runs under prefetch slack).
        const int er = lid >> 2;
        const int ec = (lid & 3) * 2;
#pragma unroll
        for (int mi = 0; mi < 4; mi++) {
            float* r0 = C + (size_t)(m0 + m_off + mi * 16 + er) * OUT_F + n0 + n_off;
            float* r1 = r0 + (size_t)8 * OUT_F;
#pragma unroll
            for (int nf = 0; nf < 8; nf++) {
                float2 v0 = make_float2(acc[mi][nf][0], acc[mi][nf][1]);
                float2 v1 = make_float2(acc[mi][nf][2], acc[mi][nf][3]);
                *reinterpret_cast<float2*>(r0 + nf * 8 + ec) = v0;
                *reinterpret_cast<float2*>(r1 + nf * 8 + ec) = v1;
            }
        }
    }
}

// ---------------- launch -----------------------------------------------------
extern "C" void kernel_launch(void* const* d_in, const int* in_sizes, int n_in,
                              void* d_out, int out_size) {
    const float* x  = (const float*)d_in[0];
    const int*   wp = (const int*)d_in[1];
    const float* ws = (const float*)d_in[2];
    float* out = (float*)d_out;

    cudaFuncSetAttribute(gemm_hmma_kernel,
                         cudaFuncAttributeMaxDynamicSharedMemorySize, SMEM_BYTES);

    int dev = 0, nsm = 148;
    cudaGetDevice(&dev);
    cudaDeviceGetAttribute(&nsm, cudaDevAttrMultiProcessorCount, dev);
    if (nsm <= 0 || nsm > N_TILES) nsm = 148;

    {
        size_t n4 = (size_t)TOKENS * IN_F / 4;
        prep_kernel<<<(unsigned)((n4 + 255) / 256), 256>>>(x, wp, ws);
    }
    {
        gemm_hmma_kernel<<<nsm, 256, SMEM_BYTES>>>(out);
    }
}

// round 14
// speedup vs baseline: 1.0589x; 1.0589x over previous
#include <cuda_runtime.h>
#include <cuda_fp16.h>
#include <cstdint>

#define TOKENS 8192
#define IN_F   4096
#define OUT_F  4096
#define BM 128
#define BN 128
#define BK 64
#define NK_ITERS (IN_F / BK)    // 64
#define LDSR (BK + 8)           // 72 halves = 144B pitch (conflict-free ldmatrix)
#define STAGES 3
#define A_STAGE_ELEMS (BM * LDSR)   // 9216
#define B_STAGE_ELEMS (BN * LDSR)   // 9216
#define SMEM_BYTES (STAGES * (A_STAGE_ELEMS + B_STAGE_ELEMS) * 2)   // 110592 (108 KB) -> 2 CTAs/SM

// ---------------- scratch (device globals: allowed; no allocs) -------------
__device__ __align__(16) __half g_Xh[(size_t)TOKENS * IN_F];   // 64 MB fp16 activations
__device__ __align__(16) __half g_Wh[(size_t)OUT_F * IN_F];    // 32 MB fp16 dequant weights

__device__ __forceinline__ uint32_t smem_u32(const void* p) {
    return (uint32_t)__cvta_generic_to_shared(p);
}

__device__ __forceinline__ void ldm_x4(uint32_t& r0, uint32_t& r1,
                                       uint32_t& r2, uint32_t& r3, uint32_t addr) {
    asm volatile("ldmatrix.sync.aligned.m8n8.x4.shared.b16 {%0,%1,%2,%3}, [%4];"
                 : "=r"(r0), "=r"(r1), "=r"(r2), "=r"(r3) : "r"(addr));
}

__device__ __forceinline__ void mma16816(float* c, const uint32_t* a,
                                         uint32_t b0, uint32_t b1) {
    asm volatile(
        "mma.sync.aligned.m16n8k16.row.col.f32.f16.f16.f32 "
        "{%0,%1,%2,%3}, {%4,%5,%6,%7}, {%8,%9}, {%0,%1,%2,%3};"
        : "+f"(c[0]), "+f"(c[1]), "+f"(c[2]), "+f"(c[3])
        : "r"(a[0]), "r"(a[1]), "r"(a[2]), "r"(a[3]), "r"(b0), "r"(b1));
}

// ---------------- fused prep kernel -----------------------------------------
// Same element count for both jobs: TOKENS*IN_F/4 = OUT_F*IN_F/2 = 8.39M.
__global__ void prep_kernel(const float* __restrict__ x,
                            const int* __restrict__ wp,
                            const float* __restrict__ ws) {
    size_t i = (size_t)blockIdx.x * blockDim.x + threadIdx.x;
    if (i >= (size_t)TOKENS * IN_F / 4) return;
    // X: one float4 -> 2x half2
    {
        float4 v = reinterpret_cast<const float4*>(x)[i];
        __half2* out = reinterpret_cast<__half2*>(g_Xh);
        out[2 * i]     = __floats2half2_rn(v.x, v.y);
        out[2 * i + 1] = __floats2half2_rn(v.z, v.w);
    }
    // W: one packed byte-pair (int32 holding uint8) -> half2
    {
        int n = (int)(i >> 11);          // / 2048
        int j = (int)(i & 2047);
        int p = wp[i];
        float s = ws[n * (IN_F / 128) + (j >> 6)];   // group = (2j)/128 = j/64
        float lo = (float)((p & 15) - 8) * s;
        float hi = (float)(((p >> 4) & 15) - 8) * s;
        reinterpret_cast<__half2*>(g_Wh)[i] = __floats2half2_rn(lo, hi);
    }
}

// ---------------- HMMA GEMM -------------------------------------------------
// C[M,N] = Xh[M,K] @ Wh[N,K]^T. CTA tile 128x128, 128 threads (4 warps, 2x2),
// warp tile 64x64, BK=64, 3-stage cp.async. TWO CTAs co-reside per SM: each
// SMSP holds one warp from each CTA, so one CTA's barrier/LDSM-warm-up bubble
// is covered by the other CTA's MMA stream (fix for tensor=74% @ occ=12.5%).
// Round-8-proven schedule: wait_group 1, refill quarter after each kk's MMA
// block, commit at kk=3 (full-iteration slack before the consuming wait).
__global__ void __launch_bounds__(128, 2)
gemm_hmma_kernel(float* __restrict__ C) {
    extern __shared__ __align__(16) __half smem[];
    __half* sA = smem;                                 // STAGES x BM x LDSR
    __half* sB = smem + STAGES * A_STAGE_ELEMS;        // STAGES x BN x LDSR

    const int tid = threadIdx.x;
    const int wid = tid >> 5;
    const int lid = tid & 31;
    const int quad = lid >> 3;
    const int l8 = lid & 7;
    const int m0 = blockIdx.y * BM;
    const int n0 = blockIdx.x * BN;
    const int m_off = (wid & 1) * 64;      // 2 warp rows
    const int n_off = (wid >> 1) * 64;     // 2 warp cols

    const __half* baseA = g_Xh + (size_t)m0 * IN_F;
    const __half* baseB = g_Wh + (size_t)n0 * IN_F;

    float acc[4][8][4];
#pragma unroll
    for (int mi = 0; mi < 4; mi++)
#pragma unroll
        for (int nf = 0; nf < 8; nf++)
#pragma unroll
            for (int r = 0; r < 4; r++) acc[mi][nf][r] = 0.0f;

    // Stage loader quarter q (0..3): A chunks tid+128*(2q), tid+128*(2q+1);
    // B chunks likewise. 8 chunks(16B) per 128B row; 1024 chunks per tile.
    auto load_quarter = [&](int st, int kc, int q) {
        const __half* pa = baseA + kc * BK;
        const __half* pb = baseB + kc * BK;
        __half* da = sA + st * A_STAGE_ELEMS;
        __half* db = sB + st * B_STAGE_ELEMS;
#pragma unroll
        for (int i = 0; i < 2; i++) {
            int chunk = tid + 128 * (2 * q + i);
            int row = chunk >> 3, ch = chunk & 7;
            uint32_t dsta = smem_u32(da + row * LDSR + ch * 8);
            uint32_t dstb = smem_u32(db + row * LDSR + ch * 8);
            asm volatile("cp.async.cg.shared.global [%0], [%1], 16;"
                         :: "r"(dsta), "l"((const void*)(pa + (size_t)row * IN_F + ch * 8)));
            asm volatile("cp.async.cg.shared.global [%0], [%1], 16;"
                         :: "r"(dstb), "l"((const void*)(pb + (size_t)row * IN_F + ch * 8)));
        }
    };

#pragma unroll
    for (int q = 0; q < 4; q++) load_quarter(0, 0, q);
    asm volatile("cp.async.commit_group;");
#pragma unroll
    for (int q = 0; q < 4; q++) load_quarter(1, 1, q);
    asm volatile("cp.async.commit_group;");

    int cur = 0;
    for (int kc = 0; kc < NK_ITERS; kc++) {
        asm volatile("cp.async.wait_group 1;");   // stage `cur` complete
        __syncthreads();                          // all warps done with stage (cur+2)%3

        const __half* cA = sA + cur * A_STAGE_ELEMS;
        const __half* cB = sB + cur * B_STAGE_ELEMS;
        const bool refill = (kc + 2 < NK_ITERS);
        const int next_st = (cur + 2) % STAGES;

#pragma unroll
        for (int kk = 0; kk < 4; kk++) {
            const int k0 = kk * 16;
            uint32_t a[4][4];
#pragma unroll
            for (int mi = 0; mi < 4; mi++) {
                uint32_t addr = smem_u32(
                    cA + (m_off + mi * 16 + (quad & 1) * 8 + l8) * LDSR
                       + k0 + (quad >> 1) * 8);
                ldm_x4(a[mi][0], a[mi][1], a[mi][2], a[mi][3], addr);
            }
            uint32_t b[4][4];
#pragma unroll
            for (int nb = 0; nb < 4; nb++) {
                uint32_t addr = smem_u32(
                    cB + (n_off + nb * 16 + (quad >> 1) * 8 + l8) * LDSR
                       + k0 + (quad & 1) * 8);
                ldm_x4(b[nb][0], b[nb][1], b[nb][2], b[nb][3], addr);
            }
#pragma unroll
            for (int mi = 0; mi < 4; mi++)
#pragma unroll
                for (int nf = 0; nf < 8; nf++) {
                    const uint32_t* bf = &b[nf >> 1][(nf & 1) * 2];
                    mma16816(acc[mi][nf], a[mi], bf[0], bf[1]);
                }

            // Interleaved refill: one quarter per kk-step, commit on the last.
            if (refill) load_quarter(next_st, kc + 2, kk);
            if (kk == 3) asm volatile("cp.async.commit_group;");
        }

        cur = (cur + 1) % STAGES;
    }

    // Epilogue: c0,c1 at (row = t/4, col = 2*(t%4)); c2,c3 at row+8.
    const int er = lid >> 2;
    const int ec = (lid & 3) * 2;
#pragma unroll
    for (int mi = 0; mi < 4; mi++) {
        float* r0 = C + (size_t)(m0 + m_off + mi * 16 + er) * OUT_F + n0 + n_off;
        float* r1 = r0 + (size_t)8 * OUT_F;
#pragma unroll
        for (int nf = 0; nf < 8; nf++) {
            float2 v0 = make_float2(acc[mi][nf][0], acc[mi][nf][1]);
            float2 v1 = make_float2(acc[mi][nf][2], acc[mi][nf][3]);
            *reinterpret_cast<float2*>(r0 + nf * 8 + ec) = v0;
            *reinterpret_cast<float2*>(r1 + nf * 8 + ec) = v1;
        }
    }
}

// ---------------- launch -----------------------------------------------------
extern "C" void kernel_launch(void* const* d_in, const int* in_sizes, int n_in,
                              void* d_out, int out_size) {
    const float* x  = (const float*)d_in[0];
    const int*   wp = (const int*)d_in[1];
    const float* ws = (const float*)d_in[2];
    float* out = (float*)d_out;

    cudaFuncSetAttribute(gemm_hmma_kernel,
                         cudaFuncAttributeMaxDynamicSharedMemorySize, SMEM_BYTES);

    {
        size_t n4 = (size_t)TOKENS * IN_F / 4;
        prep_kernel<<<(unsigned)((n4 + 255) / 256), 256>>>(x, wp, ws);
    }
    {
        dim3 grid(OUT_F / BN, TOKENS / BM);   // 32 x 64 = 2048 CTAs
        gemm_hmma_kernel<<<grid, 128, SMEM_BYTES>>>(out);
    }
}